// round 8
// baseline (speedup 1.0000x reference)
#include <cuda_runtime.h>
#include <cstdint>
#include <float.h>

#define N_NODES 50000
#define E_RAW   800000
#define E_TOT   850000   // E_RAW + N_NODES self loops
#define H1      15
#define F1      120      // H1*8
#define DIN     128
#define F2      32

#define FULL 0xFFFFFFFFu
#define NSCAN_BLK 98     // ceil(N_NODES / 512)

// ---------------- scratch (device globals; no allocation allowed) ----------------
__device__ int      g_src[(size_t)E_TOT];
__device__ int      g_dst[(size_t)E_TOT];
__device__ int      g_cnt[(size_t)N_NODES];
__device__ int      g_cursor[(size_t)N_NODES];
__device__ int      g_rowstart[(size_t)N_NODES + 1];
__device__ int      g_csr_src[(size_t)E_TOT];
__device__ int      g_part[128];
__device__ int      g_partoff[128];
__device__ unsigned g_is64;                            // edge dtype flag
__device__ float    g_xl1[(size_t)N_NODES * F1];
__device__ float    g_xr1[(size_t)N_NODES * F1];
__device__ float    g_h[(size_t)N_NODES * F1];         // layer-1 activations (post ELU)
__device__ float    g_hl2[(size_t)N_NODES * F2];
__device__ float    g_hr2[(size_t)N_NODES * F2];

__device__ __forceinline__ float lrelu(float v) { return v > 0.f ? v : 0.2f * v; }

// ---------------- edge dtype detection (sampled; 1 block) ----------------
// int64 edges (<50000): every odd 32-bit word is 0. int32 edges: odd words are
// random node ids; P[4096 sampled words all zero] ~ (1/50000)^4096 ~ 0.
__global__ void k_detect(const int* __restrict__ ei_raw) {
    unsigned acc = 0;
    for (int i = threadIdx.x; i < 4096; i += 256)
        acc |= (unsigned)ei_raw[2 * i + 1];
#pragma unroll
    for (int o = 16; o; o >>= 1) acc |= __shfl_xor_sync(FULL, acc, o);
    if ((threadIdx.x & 31) == 0 && acc) atomicOr(&g_is64, 1u);
}

// ---------------- init ----------------
__global__ void k_init() {
    int i = blockIdx.x * blockDim.x + threadIdx.x;
    if (i == 0) g_is64 = 0u;
    if (i < N_NODES) { g_cnt[i] = 0; g_cursor[i] = 0; }
}

// ---------------- normalize edges to int32 + self loops + degree count ----------------
__global__ void k_convert_count(const int* __restrict__ ei_raw) {
    int e = blockIdx.x * blockDim.x + threadIdx.x;
    if (e >= E_TOT) return;
    int src, dst;
    if (e >= E_RAW) {
        src = dst = e - E_RAW;
    } else if (g_is64) {           // flag set -> data is int32
        src = ei_raw[e];
        dst = ei_raw[E_RAW + e];
    } else {                       // int64 data: low word at 2*index
        src = ei_raw[2 * e];
        dst = ei_raw[2 * (E_RAW + e)];
    }
    g_src[e] = src;
    g_dst[e] = dst;
    atomicAdd(&g_cnt[dst], 1);
}

// ---------------- parallel scan: pass A (block partial sums) ----------------
__global__ void k_scan_a() {
    int idx = blockIdx.x * 512 + threadIdx.x;
    int v = (idx < N_NODES) ? g_cnt[idx] : 0;
#pragma unroll
    for (int o = 16; o; o >>= 1) v += __shfl_down_sync(FULL, v, o);
    __shared__ int ws[16];
    if ((threadIdx.x & 31) == 0) ws[threadIdx.x >> 5] = v;
    __syncthreads();
    if (threadIdx.x < 16) {
        int s = ws[threadIdx.x];
#pragma unroll
        for (int o = 8; o; o >>= 1) s += __shfl_down_sync(0xFFFFu, s, o);
        if (threadIdx.x == 0) g_part[blockIdx.x] = s;
    }
}

// ---------------- parallel scan: pass B (scan 98 partials; 1 block x 128) ----------------
__global__ void k_scan_b() {
    int t = threadIdx.x;                       // 128 threads
    int v = (t < NSCAN_BLK) ? g_part[t] : 0;
    int lane = t & 31, wid = t >> 5;
    int inc = v;
#pragma unroll
    for (int o = 1; o < 32; o <<= 1) {
        int u = __shfl_up_sync(FULL, inc, o);
        if (lane >= o) inc += u;
    }
    __shared__ int ws[4];
    if (lane == 31) ws[wid] = inc;
    __syncthreads();
    int woff = 0;
    for (int i = 0; i < wid; i++) woff += ws[i];
    g_partoff[t] = inc - v + woff;             // exclusive
    if (t == 0) g_rowstart[N_NODES] = E_TOT;
}

// ---------------- parallel scan: pass C (block exclusive scan + offset) ----------------
__global__ void k_scan_c() {
    int idx = blockIdx.x * 512 + threadIdx.x;
    int v = (idx < N_NODES) ? g_cnt[idx] : 0;
    int lane = threadIdx.x & 31, wid = threadIdx.x >> 5;
    int inc = v;
#pragma unroll
    for (int o = 1; o < 32; o <<= 1) {
        int u = __shfl_up_sync(FULL, inc, o);
        if (lane >= o) inc += u;
    }
    __shared__ int ws[16];
    if (lane == 31) ws[wid] = inc;
    __syncthreads();
    if (threadIdx.x < 16) {
        int s = ws[threadIdx.x];
#pragma unroll
        for (int o = 1; o < 16; o <<= 1) {
            int u = __shfl_up_sync(0xFFFFu, s, o);
            if (threadIdx.x >= o) s += u;
        }
        ws[threadIdx.x] = s;
    }
    __syncthreads();
    int woff = wid ? ws[wid - 1] : 0;
    if (idx < N_NODES)
        g_rowstart[idx] = inc - v + woff + g_partoff[blockIdx.x];
}

// ---------------- fill CSR (src ids grouped by dst) ----------------
__global__ void k_fill() {
    int e = blockIdx.x * blockDim.x + threadIdx.x;
    if (e >= E_TOT) return;
    int dst = g_dst[e];
    int pos = g_rowstart[dst] + atomicAdd(&g_cursor[dst], 1);
    g_csr_src[pos] = g_src[e];
}

// ---------------- GEMM1: smem x-tile, warp = 8 nodes x ONE matrix ----------------
__global__ void k_gemm1(const float* __restrict__ x,
                        const float* __restrict__ Wl,
                        const float* __restrict__ Wr) {
    __shared__ float4 sx[32 * 32];              // 32 nodes x 128 floats = 16KB
    int tid = threadIdx.x;
    int nb0 = blockIdx.x * 32;

    const float4* x4 = (const float4*)x + (size_t)nb0 * 32;
    for (int i = tid; i < 32 * 32; i += 256)
        if (nb0 + (i >> 5) < N_NODES) sx[i] = x4[i];
    __syncthreads();

    int w = tid >> 5, lane = tid & 31;
    int mat = w & 1;
    int l0 = (w >> 1) * 8;
    int nb = nb0 + l0;
    if (nb >= N_NODES) return;                  // N % 8 == 0 -> whole group valid

    const float4* w4 = (const float4*)(mat ? Wr : Wl);   // row k -> k*30 + g
    float* outp = mat ? g_xr1 : g_xl1;
    int g = lane < 30 ? lane : 0;               // lanes 30,31 compute garbage, never store

    float4 acc[8];
#pragma unroll
    for (int j = 0; j < 8; j++) acc[j] = make_float4(0, 0, 0, 0);

    for (int kq = 0; kq < 32; kq++) {
        float4 w0 = __ldg(&w4[(size_t)(kq * 4 + 0) * 30 + g]);
        float4 w1 = __ldg(&w4[(size_t)(kq * 4 + 1) * 30 + g]);
        float4 w2 = __ldg(&w4[(size_t)(kq * 4 + 2) * 30 + g]);
        float4 w3 = __ldg(&w4[(size_t)(kq * 4 + 3) * 30 + g]);
#pragma unroll
        for (int j = 0; j < 8; j++) {
            float4 xj = sx[(l0 + j) * 32 + kq];   // broadcast LDS.128
            acc[j].x += xj.x * w0.x + xj.y * w1.x + xj.z * w2.x + xj.w * w3.x;
            acc[j].y += xj.x * w0.y + xj.y * w1.y + xj.z * w2.y + xj.w * w3.y;
            acc[j].z += xj.x * w0.z + xj.y * w1.z + xj.z * w2.z + xj.w * w3.z;
            acc[j].w += xj.x * w0.w + xj.y * w1.w + xj.z * w2.w + xj.w * w3.w;
        }
    }
    if (lane < 30) {
#pragma unroll
        for (int j = 0; j < 8; j++)
            *(float4*)(outp + (size_t)(nb + j) * F1 + lane * 4) = acc[j];
    }
}

// ---------------- layer1 aggregate: warp per dst node, CSR, fully fused ----------------
// acc = sum_e exp(<lrelu(xl[src]+xr[dst]),att>) * xl[src]; then /den + bias, ELU -> g_h
__global__ void k_agg1(const float* __restrict__ att, const float* __restrict__ b1) {
    int dst = (blockIdx.x * blockDim.x + threadIdx.x) >> 5;
    int lane = threadIdx.x & 31;
    if (dst >= N_NODES) return;
    int g = lane < 30 ? lane : 0;

    float4 b = *((const float4*)(g_xr1 + (size_t)dst * F1) + g);
    float4 at = __ldg((const float4*)att + g);
    int s0 = g_rowstart[dst], s1 = g_rowstart[dst + 1];

    float4 acc = make_float4(0, 0, 0, 0);
    float den = 0.f;
    for (int i = s0; i < s1; i++) {
        int src = g_csr_src[i];                 // uniform across warp
        float4 a = __ldg((const float4*)(g_xl1 + (size_t)src * F1) + g);
        float p = lrelu(a.x + b.x) * at.x + lrelu(a.y + b.y) * at.y +
                  lrelu(a.z + b.z) * at.z + lrelu(a.w + b.w) * at.w;
        float p2 = __shfl_down_sync(FULL, p, 1);
        float ee = expf(p + p2);                // head value valid on even lanes < 30
        float w = __shfl_sync(FULL, ee, lane & 30);
        acc.x += w * a.x; acc.y += w * a.y; acc.z += w * a.z; acc.w += w * a.w;
        if ((lane & 1) == 0) den += ee;
    }
    float d = __shfl_sync(FULL, den, lane & 30);
    if (lane < 30) {
        float4 bv = __ldg((const float4*)b1 + g);
        float inv = 1.f / d;
        float4 v;
        v.x = acc.x * inv + bv.x; v.y = acc.y * inv + bv.y;
        v.z = acc.z * inv + bv.z; v.w = acc.w * inv + bv.w;
        v.x = v.x > 0.f ? v.x : expm1f(v.x);
        v.y = v.y > 0.f ? v.y : expm1f(v.y);
        v.z = v.z > 0.f ? v.z : expm1f(v.z);
        v.w = v.w > 0.f ? v.w : expm1f(v.w);
        *(float4*)(g_h + (size_t)dst * F1 + lane * 4) = v;
    }
}

// ---------------- GEMM2: smem x-tile, warp = 8 nodes x ONE matrix, lane = col ----------------
__global__ void k_gemm2(const float* __restrict__ Wl, const float* __restrict__ Wr) {
    __shared__ float4 sx[32 * 30];              // 32 nodes x 120 floats = 15.4KB
    int tid = threadIdx.x;
    int nb0 = blockIdx.x * 32;

    const float4* h4 = (const float4*)g_h + (size_t)nb0 * 30;
    for (int i = tid; i < 32 * 30; i += 256)
        if (nb0 + i / 30 < N_NODES) sx[i] = h4[i];
    __syncthreads();

    int w = tid >> 5, lane = tid & 31;
    int mat = w & 1;
    int l0 = (w >> 1) * 8;
    int nb = nb0 + l0;
    if (nb >= N_NODES) return;

    const float* W = mat ? Wr : Wl;             // [F1, F2] row-major, lane = col
    float* outp = mat ? g_hr2 : g_hl2;

    float acc[8] = {0, 0, 0, 0, 0, 0, 0, 0};
    for (int kq = 0; kq < 30; kq++) {
        float w0 = __ldg(&W[(size_t)(kq * 4 + 0) * F2 + lane]);
        float w1 = __ldg(&W[(size_t)(kq * 4 + 1) * F2 + lane]);
        float w2 = __ldg(&W[(size_t)(kq * 4 + 2) * F2 + lane]);
        float w3 = __ldg(&W[(size_t)(kq * 4 + 3) * F2 + lane]);
#pragma unroll
        for (int j = 0; j < 8; j++) {
            float4 xj = sx[(l0 + j) * 30 + kq];
            acc[j] += xj.x * w0 + xj.y * w1 + xj.z * w2 + xj.w * w3;
        }
    }
#pragma unroll
    for (int j = 0; j < 8; j++)
        outp[(size_t)(nb + j) * F2 + lane] = acc[j];
}

// ---------------- layer2 aggregate + bias + log_softmax: warp per dst node ----------------
__global__ void k_agg2(const float* __restrict__ att2, const float* __restrict__ b2,
                       float* __restrict__ out) {
    int dst = (blockIdx.x * blockDim.x + threadIdx.x) >> 5;
    int lane = threadIdx.x & 31;
    if (dst >= N_NODES) return;

    float b = g_hr2[(size_t)dst * F2 + lane];
    float at = __ldg(&att2[lane]);
    int s0 = g_rowstart[dst], s1 = g_rowstart[dst + 1];

    float acc = 0.f, den = 0.f;
    for (int i = s0; i < s1; i++) {
        int src = g_csr_src[i];
        float a = g_hl2[(size_t)src * F2 + lane];
        float t = lrelu(a + b) * at;
#pragma unroll
        for (int o = 16; o; o >>= 1) t += __shfl_xor_sync(FULL, t, o);
        float w = expf(t);                      // identical on all lanes
        den += w;
        acc += w * a;
    }
    float v = acc / den + __ldg(&b2[lane]);
    float m = v;
#pragma unroll
    for (int o = 16; o; o >>= 1) m = fmaxf(m, __shfl_xor_sync(FULL, m, o));
    float ex = expf(v - m);
    float s = ex;
#pragma unroll
    for (int o = 16; o; o >>= 1) s += __shfl_xor_sync(FULL, s, o);
    float ls = v - m - logf(s);
    out[(size_t)dst * F2 + lane] = v;
    out[(size_t)N_NODES * F2 + (size_t)dst * F2 + lane] = ls;
}

// ---------------- launcher ----------------
extern "C" void kernel_launch(void* const* d_in, const int* in_sizes, int n_in,
                              void* d_out, int out_size) {
    const float* x    = (const float*)d_in[0];
    const int*   ei   = (const int*)d_in[1];     // dtype detected at runtime
    const float* W1l  = (const float*)d_in[2];
    const float* W1r  = (const float*)d_in[3];
    const float* att1 = (const float*)d_in[4];
    const float* b1   = (const float*)d_in[5];
    const float* W2l  = (const float*)d_in[6];
    const float* W2r  = (const float*)d_in[7];
    const float* att2 = (const float*)d_in[8];
    const float* b2   = (const float*)d_in[9];
    float* out = (float*)d_out;

    int gblocks = (N_NODES + 31) / 32;           // 1563

    k_init<<<(N_NODES + 255) / 256, 256>>>();
    k_detect<<<1, 256>>>(ei);
    k_convert_count<<<(E_TOT + 255) / 256, 256>>>(ei);
    k_scan_a<<<NSCAN_BLK, 512>>>();
    k_scan_b<<<1, 128>>>();
    k_scan_c<<<NSCAN_BLK, 512>>>();
    k_fill<<<(E_TOT + 255) / 256, 256>>>();
    k_gemm1<<<gblocks, 256>>>(x, W1l, W1r);
    k_agg1<<<(N_NODES * 32 + 255) / 256, 256>>>(att1, b1);
    k_gemm2<<<gblocks, 256>>>(W2l, W2r);
    k_agg2<<<(N_NODES * 32 + 255) / 256, 256>>>(att2, b2, out);
}

// round 9
// speedup vs baseline: 1.1022x; 1.1022x over previous
#include <cuda_runtime.h>
#include <cstdint>
#include <float.h>

#define N_NODES 50000
#define E_RAW   800000
#define E_TOT   850000   // E_RAW + N_NODES self loops
#define H1      15
#define F1      120      // H1*8
#define DIN     128
#define F2      32

#define FULL 0xFFFFFFFFu
#define NSCAN_BLK 98     // ceil(N_NODES / 512)

// ---------------- scratch (device globals; no allocation allowed) ----------------
__device__ int      g_src[(size_t)E_TOT];
__device__ int      g_dst[(size_t)E_TOT];
__device__ int      g_cnt[(size_t)N_NODES];
__device__ int      g_cursor[(size_t)N_NODES];
__device__ int      g_rowstart[(size_t)N_NODES + 1];
__device__ int      g_csr_src[(size_t)E_TOT];
__device__ int      g_part[128];
__device__ int      g_partoff[128];
__device__ unsigned g_is64;                            // edge dtype flag
__device__ float    g_xl1[(size_t)N_NODES * F1];
__device__ float    g_xr1[(size_t)N_NODES * F1];
__device__ float    g_h[(size_t)N_NODES * F1];         // layer-1 activations (post ELU)
__device__ float    g_hl2[(size_t)N_NODES * F2];
__device__ float    g_hr2[(size_t)N_NODES * F2];

__device__ __forceinline__ float lrelu(float v) { return v > 0.f ? v : 0.2f * v; }

// ---------------- edge dtype detection (sampled; 1 block) ----------------
__global__ void k_detect(const int* __restrict__ ei_raw) {
    unsigned acc = 0;
    for (int i = threadIdx.x; i < 4096; i += 256)
        acc |= (unsigned)ei_raw[2 * i + 1];
#pragma unroll
    for (int o = 16; o; o >>= 1) acc |= __shfl_xor_sync(FULL, acc, o);
    if ((threadIdx.x & 31) == 0 && acc) atomicOr(&g_is64, 1u);
}

// ---------------- init ----------------
__global__ void k_init() {
    int i = blockIdx.x * blockDim.x + threadIdx.x;
    if (i == 0) g_is64 = 0u;
    if (i < N_NODES) { g_cnt[i] = 0; g_cursor[i] = 0; }
}

// ---------------- normalize edges to int32 + self loops + degree count ----------------
__global__ void k_convert_count(const int* __restrict__ ei_raw) {
    int e = blockIdx.x * blockDim.x + threadIdx.x;
    if (e >= E_TOT) return;
    int src, dst;
    if (e >= E_RAW) {
        src = dst = e - E_RAW;
    } else if (g_is64) {           // flag set -> data is int32
        src = ei_raw[e];
        dst = ei_raw[E_RAW + e];
    } else {                       // int64 data: low word at 2*index
        src = ei_raw[2 * e];
        dst = ei_raw[2 * (E_RAW + e)];
    }
    g_src[e] = src;
    g_dst[e] = dst;
    atomicAdd(&g_cnt[dst], 1);
}

// ---------------- parallel scan: pass A (block partial sums) ----------------
__global__ void k_scan_a() {
    int idx = blockIdx.x * 512 + threadIdx.x;
    int v = (idx < N_NODES) ? g_cnt[idx] : 0;
#pragma unroll
    for (int o = 16; o; o >>= 1) v += __shfl_down_sync(FULL, v, o);
    __shared__ int ws[16];
    if ((threadIdx.x & 31) == 0) ws[threadIdx.x >> 5] = v;
    __syncthreads();
    if (threadIdx.x < 16) {
        int s = ws[threadIdx.x];
#pragma unroll
        for (int o = 8; o; o >>= 1) s += __shfl_down_sync(0xFFFFu, s, o);
        if (threadIdx.x == 0) g_part[blockIdx.x] = s;
    }
}

// ---------------- parallel scan: pass B (scan 98 partials; 1 block x 128) ----------------
__global__ void k_scan_b() {
    int t = threadIdx.x;                       // 128 threads
    int v = (t < NSCAN_BLK) ? g_part[t] : 0;
    int lane = t & 31, wid = t >> 5;
    int inc = v;
#pragma unroll
    for (int o = 1; o < 32; o <<= 1) {
        int u = __shfl_up_sync(FULL, inc, o);
        if (lane >= o) inc += u;
    }
    __shared__ int ws[4];
    if (lane == 31) ws[wid] = inc;
    __syncthreads();
    int woff = 0;
    for (int i = 0; i < wid; i++) woff += ws[i];
    g_partoff[t] = inc - v + woff;             // exclusive
    if (t == 0) g_rowstart[N_NODES] = E_TOT;
}

// ---------------- parallel scan: pass C (block exclusive scan + offset) ----------------
__global__ void k_scan_c() {
    int idx = blockIdx.x * 512 + threadIdx.x;
    int v = (idx < N_NODES) ? g_cnt[idx] : 0;
    int lane = threadIdx.x & 31, wid = threadIdx.x >> 5;
    int inc = v;
#pragma unroll
    for (int o = 1; o < 32; o <<= 1) {
        int u = __shfl_up_sync(FULL, inc, o);
        if (lane >= o) inc += u;
    }
    __shared__ int ws[16];
    if (lane == 31) ws[wid] = inc;
    __syncthreads();
    if (threadIdx.x < 16) {
        int s = ws[threadIdx.x];
#pragma unroll
        for (int o = 1; o < 16; o <<= 1) {
            int u = __shfl_up_sync(0xFFFFu, s, o);
            if (threadIdx.x >= o) s += u;
        }
        ws[threadIdx.x] = s;
    }
    __syncthreads();
    int woff = wid ? ws[wid - 1] : 0;
    if (idx < N_NODES)
        g_rowstart[idx] = inc - v + woff + g_partoff[blockIdx.x];
}

// ---------------- fill CSR (src ids grouped by dst) ----------------
__global__ void k_fill() {
    int e = blockIdx.x * blockDim.x + threadIdx.x;
    if (e >= E_TOT) return;
    int dst = g_dst[e];
    int pos = g_rowstart[dst] + atomicAdd(&g_cursor[dst], 1);
    g_csr_src[pos] = g_src[e];
}

// ---------------- GEMM1: smem x-tile, warp = 8 nodes x ONE matrix ----------------
__global__ void k_gemm1(const float* __restrict__ x,
                        const float* __restrict__ Wl,
                        const float* __restrict__ Wr) {
    __shared__ float4 sx[32 * 32];              // 32 nodes x 128 floats = 16KB
    int tid = threadIdx.x;
    int nb0 = blockIdx.x * 32;

    const float4* x4 = (const float4*)x + (size_t)nb0 * 32;
    for (int i = tid; i < 32 * 32; i += 256)
        if (nb0 + (i >> 5) < N_NODES) sx[i] = x4[i];
    __syncthreads();

    int w = tid >> 5, lane = tid & 31;
    int mat = w & 1;
    int l0 = (w >> 1) * 8;
    int nb = nb0 + l0;
    if (nb >= N_NODES) return;                  // N % 8 == 0 -> whole group valid

    const float4* w4 = (const float4*)(mat ? Wr : Wl);   // row k -> k*30 + g
    float* outp = mat ? g_xr1 : g_xl1;
    int g = lane < 30 ? lane : 0;               // lanes 30,31 compute garbage, never store

    float4 acc[8];
#pragma unroll
    for (int j = 0; j < 8; j++) acc[j] = make_float4(0, 0, 0, 0);

    for (int kq = 0; kq < 32; kq++) {
        float4 w0 = __ldg(&w4[(size_t)(kq * 4 + 0) * 30 + g]);
        float4 w1 = __ldg(&w4[(size_t)(kq * 4 + 1) * 30 + g]);
        float4 w2 = __ldg(&w4[(size_t)(kq * 4 + 2) * 30 + g]);
        float4 w3 = __ldg(&w4[(size_t)(kq * 4 + 3) * 30 + g]);
#pragma unroll
        for (int j = 0; j < 8; j++) {
            float4 xj = sx[(l0 + j) * 32 + kq];   // broadcast LDS.128
            acc[j].x += xj.x * w0.x + xj.y * w1.x + xj.z * w2.x + xj.w * w3.x;
            acc[j].y += xj.x * w0.y + xj.y * w1.y + xj.z * w2.y + xj.w * w3.y;
            acc[j].z += xj.x * w0.z + xj.y * w1.z + xj.z * w2.z + xj.w * w3.z;
            acc[j].w += xj.x * w0.w + xj.y * w1.w + xj.z * w2.w + xj.w * w3.w;
        }
    }
    if (lane < 30) {
#pragma unroll
        for (int j = 0; j < 8; j++)
            *(float4*)(outp + (size_t)(nb + j) * F1 + lane * 4) = acc[j];
    }
}

// ---------------- layer1 aggregate: warp per dst node, 4-wide pipelined ----------------
// acc = sum_e exp(<lrelu(xl[src]+xr[dst]),att>) * xl[src]; then /den + bias, ELU -> g_h
__global__ void k_agg1(const float* __restrict__ att, const float* __restrict__ b1) {
    int dst = (blockIdx.x * blockDim.x + threadIdx.x) >> 5;
    int lane = threadIdx.x & 31;
    if (dst >= N_NODES) return;
    int g = lane < 30 ? lane : 0;

    float4 b = *((const float4*)(g_xr1 + (size_t)dst * F1) + g);
    float4 at = __ldg((const float4*)att + g);
    int s0 = g_rowstart[dst], s1 = g_rowstart[dst + 1];

    float4 acc = make_float4(0, 0, 0, 0);
    float den = 0.f;

#define EDGE1(A)                                                                  \
    {                                                                             \
        float p = lrelu(A.x + b.x) * at.x + lrelu(A.y + b.y) * at.y +             \
                  lrelu(A.z + b.z) * at.z + lrelu(A.w + b.w) * at.w;              \
        float p2 = __shfl_down_sync(FULL, p, 1);                                  \
        float ee = __expf(p + p2);                                                \
        float w = __shfl_sync(FULL, ee, lane & 30);                               \
        acc.x += w * A.x; acc.y += w * A.y; acc.z += w * A.z; acc.w += w * A.w;   \
        if ((lane & 1) == 0) den += ee;                                           \
    }

    int i = s0;
    for (; i + 3 < s1; i += 4) {
        int sa = g_csr_src[i], sb = g_csr_src[i + 1];
        int sc = g_csr_src[i + 2], sd = g_csr_src[i + 3];
        float4 a0 = __ldg((const float4*)(g_xl1 + (size_t)sa * F1) + g);
        float4 a1 = __ldg((const float4*)(g_xl1 + (size_t)sb * F1) + g);
        float4 a2 = __ldg((const float4*)(g_xl1 + (size_t)sc * F1) + g);
        float4 a3 = __ldg((const float4*)(g_xl1 + (size_t)sd * F1) + g);
        EDGE1(a0) EDGE1(a1) EDGE1(a2) EDGE1(a3)
    }
    for (; i < s1; i++) {
        int sa = g_csr_src[i];
        float4 a0 = __ldg((const float4*)(g_xl1 + (size_t)sa * F1) + g);
        EDGE1(a0)
    }
#undef EDGE1

    float d = __shfl_sync(FULL, den, lane & 30);
    if (lane < 30) {
        float4 bv = __ldg((const float4*)b1 + g);
        float inv = 1.f / d;
        float4 v;
        v.x = acc.x * inv + bv.x; v.y = acc.y * inv + bv.y;
        v.z = acc.z * inv + bv.z; v.w = acc.w * inv + bv.w;
        v.x = v.x > 0.f ? v.x : __expf(v.x) - 1.f;
        v.y = v.y > 0.f ? v.y : __expf(v.y) - 1.f;
        v.z = v.z > 0.f ? v.z : __expf(v.z) - 1.f;
        v.w = v.w > 0.f ? v.w : __expf(v.w) - 1.f;
        *(float4*)(g_h + (size_t)dst * F1 + lane * 4) = v;
    }
}

// ---------------- GEMM2: smem x-tile, warp = 8 nodes x ONE matrix, lane = col ----------------
__global__ void k_gemm2(const float* __restrict__ Wl, const float* __restrict__ Wr) {
    __shared__ float4 sx[32 * 30];              // 32 nodes x 120 floats = 15.4KB
    int tid = threadIdx.x;
    int nb0 = blockIdx.x * 32;

    const float4* h4 = (const float4*)g_h + (size_t)nb0 * 30;
    for (int i = tid; i < 32 * 30; i += 256)
        if (nb0 + i / 30 < N_NODES) sx[i] = h4[i];
    __syncthreads();

    int w = tid >> 5, lane = tid & 31;
    int mat = w & 1;
    int l0 = (w >> 1) * 8;
    int nb = nb0 + l0;
    if (nb >= N_NODES) return;

    const float* W = mat ? Wr : Wl;             // [F1, F2] row-major, lane = col
    float* outp = mat ? g_hr2 : g_hl2;

    float acc[8] = {0, 0, 0, 0, 0, 0, 0, 0};
    for (int kq = 0; kq < 30; kq++) {
        float w0 = __ldg(&W[(size_t)(kq * 4 + 0) * F2 + lane]);
        float w1 = __ldg(&W[(size_t)(kq * 4 + 1) * F2 + lane]);
        float w2 = __ldg(&W[(size_t)(kq * 4 + 2) * F2 + lane]);
        float w3 = __ldg(&W[(size_t)(kq * 4 + 3) * F2 + lane]);
#pragma unroll
        for (int j = 0; j < 8; j++) {
            float4 xj = sx[(l0 + j) * 30 + kq];
            acc[j] += xj.x * w0 + xj.y * w1 + xj.z * w2 + xj.w * w3;
        }
    }
#pragma unroll
    for (int j = 0; j < 8; j++)
        outp[(size_t)(nb + j) * F2 + lane] = acc[j];
}

// ---------------- layer2 aggregate + bias + log_softmax: warp per dst, 4-wide ----------------
__global__ void k_agg2(const float* __restrict__ att2, const float* __restrict__ b2,
                       float* __restrict__ out) {
    int dst = (blockIdx.x * blockDim.x + threadIdx.x) >> 5;
    int lane = threadIdx.x & 31;
    if (dst >= N_NODES) return;

    float b = g_hr2[(size_t)dst * F2 + lane];
    float at = __ldg(&att2[lane]);
    int s0 = g_rowstart[dst], s1 = g_rowstart[dst + 1];

    float acc = 0.f, den = 0.f;

#define EDGE2(A)                                                    \
    {                                                               \
        float t = lrelu(A + b) * at;                                \
        _Pragma("unroll")                                           \
        for (int o = 16; o; o >>= 1) t += __shfl_xor_sync(FULL, t, o); \
        float w = __expf(t);                                        \
        den += w;                                                   \
        acc += w * A;                                               \
    }

    int i = s0;
    for (; i + 3 < s1; i += 4) {
        int sa = g_csr_src[i], sb = g_csr_src[i + 1];
        int sc = g_csr_src[i + 2], sd = g_csr_src[i + 3];
        float a0 = g_hl2[(size_t)sa * F2 + lane];
        float a1 = g_hl2[(size_t)sb * F2 + lane];
        float a2 = g_hl2[(size_t)sc * F2 + lane];
        float a3 = g_hl2[(size_t)sd * F2 + lane];
        EDGE2(a0) EDGE2(a1) EDGE2(a2) EDGE2(a3)
    }
    for (; i < s1; i++) {
        int sa = g_csr_src[i];
        float a0 = g_hl2[(size_t)sa * F2 + lane];
        EDGE2(a0)
    }
#undef EDGE2

    float v = acc / den + __ldg(&b2[lane]);
    float m = v;
#pragma unroll
    for (int o = 16; o; o >>= 1) m = fmaxf(m, __shfl_xor_sync(FULL, m, o));
    float ex = expf(v - m);
    float s = ex;
#pragma unroll
    for (int o = 16; o; o >>= 1) s += __shfl_xor_sync(FULL, s, o);
    float ls = v - m - logf(s);
    out[(size_t)dst * F2 + lane] = v;
    out[(size_t)N_NODES * F2 + (size_t)dst * F2 + lane] = ls;
}

// ---------------- launcher ----------------
extern "C" void kernel_launch(void* const* d_in, const int* in_sizes, int n_in,
                              void* d_out, int out_size) {
    const float* x    = (const float*)d_in[0];
    const int*   ei   = (const int*)d_in[1];     // dtype detected at runtime
    const float* W1l  = (const float*)d_in[2];
    const float* W1r  = (const float*)d_in[3];
    const float* att1 = (const float*)d_in[4];
    const float* b1   = (const float*)d_in[5];
    const float* W2l  = (const float*)d_in[6];
    const float* W2r  = (const float*)d_in[7];
    const float* att2 = (const float*)d_in[8];
    const float* b2   = (const float*)d_in[9];
    float* out = (float*)d_out;

    int gblocks = (N_NODES + 31) / 32;           // 1563

    k_init<<<(N_NODES + 255) / 256, 256>>>();
    k_detect<<<1, 256>>>(ei);
    k_convert_count<<<(E_TOT + 255) / 256, 256>>>(ei);
    k_scan_a<<<NSCAN_BLK, 512>>>();
    k_scan_b<<<1, 128>>>();
    k_scan_c<<<NSCAN_BLK, 512>>>();
    k_fill<<<(E_TOT + 255) / 256, 256>>>();
    k_gemm1<<<gblocks, 256>>>(x, W1l, W1r);
    k_agg1<<<(N_NODES * 32 + 255) / 256, 256>>>(att1, b1);
    k_gemm2<<<gblocks, 256>>>(W2l, W2r);
    k_agg2<<<(N_NODES * 32 + 255) / 256, 256>>>(att2, b2, out);
}